// round 14
// baseline (speedup 1.0000x reference)
#include <cuda_runtime.h>
#include <cuda_fp16.h>
#include <cuda_bf16.h>
#include <math.h>
#include <stdint.h>

// ---------------------------------------------------------------------------
// Problem constants
// ---------------------------------------------------------------------------
#define BATCH   8
#define SEQ     1024
#define ROWS    (BATCH * SEQ)        // 8192
#define EMBED   768
#define HEADS   12
#define HDIM    64
#define QKVDIM  2304                 // fused q|k|v columns
#define MLPDIM  3072
#define BH      (BATCH * HEADS)      // 96

// ---------------------------------------------------------------------------
// Device scratch (static globals — allocation-free)
// ---------------------------------------------------------------------------
__device__ __half g_qkvh[(size_t)ROWS * QKVDIM];     // fused QKV projection (f16)
__device__ float  g_x2  [(size_t)ROWS * EMBED];      // x + proj (f32)
__device__ __half g_h1h [(size_t)ROWS * EMBED];      // LN1 out (f16)
__device__ __half g_atth[(size_t)ROWS * EMBED];      // attention out (f16)
__device__ __half g_h2h [(size_t)ROWS * EMBED];      // LN2 out (f16)
__device__ __half g_m1h [(size_t)ROWS * MLPDIM];     // GELU(fc1) (f16)
__device__ __half g_qkv_wt[(size_t)QKVDIM * EMBED];  // [2304][768] half
__device__ __half g_proj_wt[(size_t)EMBED * EMBED];  // [768][768]
__device__ __half g_fc1_wt[(size_t)MLPDIM * EMBED];  // [3072][768]
__device__ __half g_fc2_wt[(size_t)EMBED * MLPDIM];  // [768][3072]

// ---------------------------------------------------------------------------
// Helpers
// ---------------------------------------------------------------------------
__device__ __forceinline__ void mma_f16(float c[4],
                                        const uint32_t a[4],
                                        const uint32_t b[2]) {
    asm volatile(
        "mma.sync.aligned.m16n8k16.row.col.f32.f16.f16.f32 "
        "{%0,%1,%2,%3}, {%4,%5,%6,%7}, {%8,%9}, {%0,%1,%2,%3};"
        : "+f"(c[0]), "+f"(c[1]), "+f"(c[2]), "+f"(c[3])
        : "r"(a[0]), "r"(a[1]), "r"(a[2]), "r"(a[3]),
          "r"(b[0]), "r"(b[1]));
}

#define LDMX4(r0, r1, r2, r3, addr)                                       \
    asm volatile("ldmatrix.sync.aligned.m8n8.x4.shared.b16 "              \
                 "{%0,%1,%2,%3}, [%4];"                                   \
                 : "=r"(r0), "=r"(r1), "=r"(r2), "=r"(r3) : "r"(addr))

#define LDMX4T(r0, r1, r2, r3, addr)                                      \
    asm volatile("ldmatrix.sync.aligned.m8n8.x4.trans.shared.b16 "        \
                 "{%0,%1,%2,%3}, [%4];"                                   \
                 : "=r"(r0), "=r"(r1), "=r"(r2), "=r"(r3) : "r"(addr))

__device__ __forceinline__ void cp16(uint32_t dst, const void* src) {
    asm volatile("cp.async.cg.shared.global [%0], [%1], 16;" :: "r"(dst), "l"(src));
}
__device__ __forceinline__ void cp_commit() {
    asm volatile("cp.async.commit_group;");
}
__device__ __forceinline__ void cp_wait1() {
    asm volatile("cp.async.wait_group 1;");
}

// ---------------------------------------------------------------------------
// Weight transpose+convert: W [K][N] f32 -> Wt [N][K] f16
// ---------------------------------------------------------------------------
__global__ __launch_bounds__(256)
void wtrans(const float* __restrict__ W, __half* __restrict__ Wt, int K, int N)
{
    __shared__ __half t[32][33];
    const int n0 = blockIdx.x * 32, k0 = blockIdx.y * 32;
    const int tx = threadIdx.x & 31, ty = threadIdx.x >> 5;
    #pragma unroll
    for (int i = 0; i < 4; i++)
        t[ty + i * 8][tx] = __float2half_rn(W[(long)(k0 + ty + i * 8) * N + n0 + tx]);
    __syncthreads();
    #pragma unroll
    for (int i = 0; i < 4; i++)
        Wt[(long)(n0 + ty + i * 8) * K + k0 + tx] = t[tx][ty + i * 8];
}

// ---------------------------------------------------------------------------
// LayerNorm v2: warp per row, float4 loads, pure shuffle reduce.
// Block 256 = 8 rows. Grid ROWS/8.
// ---------------------------------------------------------------------------
__global__ __launch_bounds__(256)
void ln_half(const float* __restrict__ x, const float* __restrict__ g,
             const float* __restrict__ b, __half* __restrict__ out)
{
    const int lane = threadIdx.x & 31;
    const long row = (long)blockIdx.x * 8 + (threadIdx.x >> 5);
    const float* p = x + row * EMBED;

    float4 v[6];
    float s = 0.0f, q = 0.0f;
    #pragma unroll
    for (int i = 0; i < 6; i++) {
        v[i] = *(const float4*)(p + lane * 4 + i * 128);
        s += v[i].x + v[i].y + v[i].z + v[i].w;
        q += v[i].x * v[i].x + v[i].y * v[i].y + v[i].z * v[i].z + v[i].w * v[i].w;
    }
    #pragma unroll
    for (int o = 16; o; o >>= 1) {
        s += __shfl_xor_sync(0xFFFFFFFFu, s, o);
        q += __shfl_xor_sync(0xFFFFFFFFu, q, o);
    }
    const float inv = 1.0f / (float)EMBED;
    const float mu  = s * inv;
    const float var = q * inv - mu * mu;
    const float rstd = rsqrtf(var + 1e-5f);

    __half* po = out + row * EMBED;
    #pragma unroll
    for (int i = 0; i < 6; i++) {
        const int col = lane * 4 + i * 128;
        const float4 gv = *(const float4*)(g + col);
        const float4 bv = *(const float4*)(b + col);
        __half2 h0 = __floats2half2_rn((v[i].x - mu) * rstd * gv.x + bv.x,
                                       (v[i].y - mu) * rstd * gv.y + bv.y);
        __half2 h1 = __floats2half2_rn((v[i].z - mu) * rstd * gv.z + bv.z,
                                       (v[i].w - mu) * rstd * gv.w + bv.w);
        uint2 u;
        u.x = *(uint32_t*)&h0;
        u.y = *(uint32_t*)&h1;
        *(uint2*)(po + col) = u;
    }
}

// ---------------------------------------------------------------------------
// FP16 ldmatrix GEMM v3: 128x256 block tile, warp tile 64x64, BK=64,
// 3-stage cp.async, one barrier per k-tile. 256 threads (8 warps 2x4).
// Per k-tile per warp: 32 LDSM + 128 mma (~75% mma issue fraction).
// Smem: stage s @ s*55296 (A 128 rows @ +0, B 256 rows @ +18432),
// row stride 144 B. 3 stages = 165888 B.
// ---------------------------------------------------------------------------
#define EPI_NONE     0
#define EPI_GELU     2
#define EPI_BIASRES  3

#define GEMM_SMEM_BYTES 165888

template<int EPI, int OUTH>
__global__ __launch_bounds__(256, 1)
void gemm_h(const __half* __restrict__ A, const __half* __restrict__ Bt,
            const float* __restrict__ bias, const float* __restrict__ res,
            void* __restrict__ Cv, int M, int N, int K)
{
    extern __shared__ __align__(16) uint8_t sgb[];
    const uint32_t sbase = (uint32_t)__cvta_generic_to_shared(sgb);

    const int tid  = threadIdx.x;
    const int bm   = blockIdx.y * 128;
    const int bn   = blockIdx.x * 256;
    const int w    = tid >> 5;
    const int lane = tid & 31;
    const int m0   = (w >> 2) * 64;    // 0 or 64
    const int n0   = (w & 3) * 64;     // 0..192
    const int g    = lane >> 2;
    const int tq   = lane & 3;

    // A loader: 128 rows, 2 thr/row, 4 cp16 each (128 B/row)
    const int arow = tid >> 1;
    const int aside = tid & 1;
    const __half* Ag = A + (long)(bm + arow) * K + aside * 32;
    const uint32_t adst = sbase + arow * 144 + aside * 64;
    // B loader: 256 rows, 1 thr/row, 8 cp16 (128 B/row)
    const __half* Bg = Bt + (long)(bn + tid) * K;
    const uint32_t bdst = sbase + 18432 + tid * 144;

    const int lr = lane & 15, lh = lane >> 4;
    const uint32_t a_lm = sbase + (m0 + lr) * 144 + lh * 16;
    const uint32_t b_lm = sbase + 18432 + (n0 + lr) * 144 + lh * 16;

    float acc[4][8][4];
    #pragma unroll
    for (int i = 0; i < 4; i++)
        #pragma unroll
        for (int j = 0; j < 8; j++)
            #pragma unroll
            for (int r = 0; r < 4; r++) acc[i][j][r] = 0.0f;

    auto issue = [&](int t, int s) {
        const uint32_t off = s * 55296;
        const __half* ap = Ag + t * 64;
        const __half* bp = Bg + t * 64;
        #pragma unroll
        for (int i = 0; i < 4; i++) cp16(adst + off + i * 16, ap + i * 8);
        #pragma unroll
        for (int i = 0; i < 8; i++) cp16(bdst + off + i * 16, bp + i * 8);
    };

    const int NT = K >> 6;           // 12 or 48
    issue(0, 0); cp_commit();
    issue(1, 1); cp_commit();

    int st = 0;
    for (int t = 0; t < NT; t++) {
        cp_wait1();                  // tile t landed; t+1 in flight
        __syncthreads();             // + stage (t+2)%3 reads (iter t-1) done

        int s2 = st + 2; if (s2 >= 3) s2 -= 3;
        if (t + 2 < NT) issue(t + 2, s2);
        cp_commit();

        const uint32_t soff = st * 55296;
        #pragma unroll
        for (int ks = 0; ks < 4; ks++) {
            uint32_t af[4][4];
            #pragma unroll
            for (int i = 0; i < 4; i++)
                LDMX4(af[i][0], af[i][1], af[i][2], af[i][3],
                      a_lm + soff + i * 2304 + ks * 32);
            uint32_t bf[8][2];
            #pragma unroll
            for (int p = 0; p < 4; p++) {
                uint32_t q0, q1, q2, q3;
                LDMX4(q0, q1, q2, q3, b_lm + soff + p * 2304 + ks * 32);
                bf[2 * p    ][0] = q0; bf[2 * p + 1][0] = q1;
                bf[2 * p    ][1] = q2; bf[2 * p + 1][1] = q3;
            }
            #pragma unroll
            for (int i = 0; i < 4; i++)
                #pragma unroll
                for (int j = 0; j < 8; j++)
                    mma_f16(acc[i][j], af[i], bf[j]);
        }
        st = (st == 2) ? 0 : st + 1;
    }

    float*  Cf = (float*)Cv;
    __half* Ch = (__half*)Cv;
    #pragma unroll
    for (int i = 0; i < 4; i++) {
        const int row0 = bm + m0 + i * 16 + g;
        #pragma unroll
        for (int j = 0; j < 8; j++) {
            const int col = bn + n0 + j * 8 + tq * 2;
            float b0 = 0.0f, b1 = 0.0f;
            if (EPI != EPI_NONE) { b0 = bias[col]; b1 = bias[col + 1]; }
            #pragma unroll
            for (int half_ = 0; half_ < 2; half_++) {
                const long base = (long)(row0 + half_ * 8) * N + col;
                float c0 = acc[i][j][half_ * 2 + 0];
                float c1 = acc[i][j][half_ * 2 + 1];
                if (EPI != EPI_NONE) { c0 += b0; c1 += b1; }
                if (EPI == EPI_GELU) {
                    c0 = 0.5f * c0 * (1.0f + erff(c0 * 0.70710678118654752f));
                    c1 = 0.5f * c1 * (1.0f + erff(c1 * 0.70710678118654752f));
                }
                if (EPI == EPI_BIASRES) { c0 += res[base]; c1 += res[base + 1]; }
                if (OUTH) {
                    *(__half2*)(Ch + base) = __floats2half2_rn(c0, c1);
                } else {
                    float2 o; o.x = c0; o.y = c1;
                    *(float2*)(Cf + base) = o;
                }
            }
        }
    }
}

// ---------------------------------------------------------------------------
// Flash attention v5 (validated R13): fp16 ldmatrix + double-buffered K/V.
// Smem bytes: Qs @0 (18432), K stage s @ 18432+s*9216, V stage s @
// 36864+s*9216, Ps @ 55296 (18432). Total 73728 B.
// ---------------------------------------------------------------------------
#define FA_SMEM_BYTES 73728

__global__ __launch_bounds__(256, 2)
void flash_h(const __half* __restrict__ qkv, __half* __restrict__ att)
{
    extern __shared__ __align__(16) uint8_t shb[];
    const uint32_t sbase = (uint32_t)__cvta_generic_to_shared(shb);
    const uint32_t KOFF = 18432;
    const uint32_t VOFF = 36864;
    const uint32_t POFF = 55296;

    const int bh = blockIdx.y;
    const int b  = bh / HEADS, h = bh % HEADS;
    const int q0 = blockIdx.x * 128;
    const int tid  = threadIdx.x;
    const int w    = tid >> 5;
    const int lane = tid & 31;
    const int g    = lane >> 2;
    const int tq   = lane & 3;
    const int lr   = lane & 15, lh = lane >> 4;

    const __half* Qg = qkv + (long)b * SEQ * QKVDIM + h * HDIM;
    const __half* Kg = Qg + EMBED;
    const __half* Vg = Qg + 2 * EMBED;

    const int qrow = tid >> 1, qside = tid & 1;
    const int kr = tid & 63, kq = (tid >> 6) * 16;   // halves

    auto issueKV = [&](int kv, int s) {
        const __half* ks = Kg + (long)(kv + kr) * QKVDIM + kq;
        const __half* vs = Vg + (long)(kv + kr) * QKVDIM + kq;
        const uint32_t kd = sbase + KOFF + s * 9216 + kr * 144 + kq * 2;
        const uint32_t vd = sbase + VOFF + s * 9216 + kr * 144 + kq * 2;
        cp16(kd, ks); cp16(kd + 16, ks + 8);
        cp16(vd, vs); cp16(vd + 16, vs + 8);
    };

    {
        const __half* src = Qg + (long)(q0 + qrow) * QKVDIM + qside * 32;
        const uint32_t dst = sbase + qrow * 144 + qside * 64;
        #pragma unroll
        for (int i = 0; i < 4; i++) cp16(dst + i * 16, src + i * 8);
    }
    issueKV(0, 0);
    cp_commit();

    const uint32_t qa_lm = sbase + (w * 16 + lr) * 144 + lh * 16;
    const uint32_t pa_lm = sbase + POFF + w * 2304 + lr * 144 + lh * 16;
    const uint32_t pw    = sbase + POFF + w * 2304;

    float oacc[8][4];
    #pragma unroll
    for (int j = 0; j < 8; j++)
        #pragma unroll
        for (int r = 0; r < 4; r++) oacc[j][r] = 0.0f;
    float mrow0 = -INFINITY, mrow1 = -INFINITY;
    float lrow0 = 0.0f, lrow1 = 0.0f;

    for (int t = 0; t < SEQ / 64; t++) {
        __syncthreads();
        if (t + 1 < SEQ / 64) issueKV((t + 1) * 64, (t + 1) & 1);
        cp_commit();
        cp_wait1();
        __syncthreads();

        const uint32_t kb_lm = sbase + KOFF + (t & 1) * 9216 + lr * 144 + lh * 16;
        const uint32_t vb_lm = sbase + VOFF + (t & 1) * 9216 + lr * 144 + lh * 16;

        float sacc[8][4];
        #pragma unroll
        for (int j = 0; j < 8; j++)
            #pragma unroll
            for (int r = 0; r < 4; r++) sacc[j][r] = 0.0f;

        #pragma unroll
        for (int ks = 0; ks < 4; ks++) {
            uint32_t af[4];
            LDMX4(af[0], af[1], af[2], af[3], qa_lm + ks * 32);
            uint32_t bf[8][2];
            #pragma unroll
            for (int p = 0; p < 4; p++) {
                uint32_t r0, r1, r2, r3;
                LDMX4(r0, r1, r2, r3, kb_lm + p * 2304 + ks * 32);
                bf[2 * p    ][0] = r0; bf[2 * p + 1][0] = r1;
                bf[2 * p    ][1] = r2; bf[2 * p + 1][1] = r3;
            }
            #pragma unroll
            for (int j = 0; j < 8; j++)
                mma_f16(sacc[j], af, bf[j]);
        }

        #pragma unroll
        for (int j = 0; j < 8; j++) {
            sacc[j][0] *= 0.125f; sacc[j][1] *= 0.125f;
            sacc[j][2] *= 0.125f; sacc[j][3] *= 0.125f;
        }
        float tmax0 = -INFINITY, tmax1 = -INFINITY;
        #pragma unroll
        for (int j = 0; j < 8; j++) {
            tmax0 = fmaxf(tmax0, fmaxf(sacc[j][0], sacc[j][1]));
            tmax1 = fmaxf(tmax1, fmaxf(sacc[j][2], sacc[j][3]));
        }
        #pragma unroll
        for (int o = 1; o < 4; o <<= 1) {
            tmax0 = fmaxf(tmax0, __shfl_xor_sync(0xFFFFFFFFu, tmax0, o));
            tmax1 = fmaxf(tmax1, __shfl_xor_sync(0xFFFFFFFFu, tmax1, o));
        }
        const float mnew0 = fmaxf(mrow0, tmax0);
        const float mnew1 = fmaxf(mrow1, tmax1);
        const float alpha0 = __expf(mrow0 - mnew0);
        const float alpha1 = __expf(mrow1 - mnew1);
        mrow0 = mnew0; mrow1 = mnew1;

        float sum0 = 0.0f, sum1 = 0.0f;
        #pragma unroll
        for (int j = 0; j < 8; j++) {
            sacc[j][0] = __expf(sacc[j][0] - mnew0);
            sacc[j][1] = __expf(sacc[j][1] - mnew0);
            sacc[j][2] = __expf(sacc[j][2] - mnew1);
            sacc[j][3] = __expf(sacc[j][3] - mnew1);
            sum0 += sacc[j][0] + sacc[j][1];
            sum1 += sacc[j][2] + sacc[j][3];
        }
        #pragma unroll
        for (int o = 1; o < 4; o <<= 1) {
            sum0 += __shfl_xor_sync(0xFFFFFFFFu, sum0, o);
            sum1 += __shfl_xor_sync(0xFFFFFFFFu, sum1, o);
        }
        lrow0 = lrow0 * alpha0 + sum0;
        lrow1 = lrow1 * alpha1 + sum1;

        #pragma unroll
        for (int j = 0; j < 8; j++) {
            oacc[j][0] *= alpha0; oacc[j][1] *= alpha0;
            oacc[j][2] *= alpha1; oacc[j][3] *= alpha1;
        }

        #pragma unroll
        for (int j = 0; j < 8; j++) {
            __half2 p0 = __floats2half2_rn(sacc[j][0], sacc[j][1]);
            __half2 p1 = __floats2half2_rn(sacc[j][2], sacc[j][3]);
            asm volatile("st.shared.b32 [%0], %1;" ::
                "r"(pw + g * 144 + (j * 8 + tq * 2) * 2),
                "r"(*(uint32_t*)&p0));
            asm volatile("st.shared.b32 [%0], %1;" ::
                "r"(pw + (g + 8) * 144 + (j * 8 + tq * 2) * 2),
                "r"(*(uint32_t*)&p1));
        }
        __syncwarp();

        #pragma unroll
        for (int ks = 0; ks < 4; ks++) {
            uint32_t af[4];
            LDMX4(af[0], af[1], af[2], af[3], pa_lm + ks * 32);
            uint32_t bf[8][2];
            #pragma unroll
            for (int p = 0; p < 4; p++) {
                uint32_t r0, r1, r2, r3;
                LDMX4T(r0, r1, r2, r3, vb_lm + ks * 16 * 144 + p * 32);
                bf[2 * p    ][0] = r0; bf[2 * p    ][1] = r1;
                bf[2 * p + 1][0] = r2; bf[2 * p + 1][1] = r3;
            }
            #pragma unroll
            for (int j = 0; j < 8; j++)
                mma_f16(oacc[j], af, bf[j]);
        }
        __syncwarp();
    }

    const float inv0 = 1.0f / lrow0;
    const float inv1 = 1.0f / lrow1;
    const long row0 = (long)(b * SEQ + q0 + w * 16 + g);
    #pragma unroll
    for (int j = 0; j < 8; j++) {
        const int col = h * HDIM + j * 8 + tq * 2;
        *(__half2*)(att + row0 * EMBED + col) =
            __floats2half2_rn(oacc[j][0] * inv0, oacc[j][1] * inv0);
        *(__half2*)(att + (row0 + 8) * EMBED + col) =
            __floats2half2_rn(oacc[j][2] * inv1, oacc[j][3] * inv1);
    }
}

// ---------------------------------------------------------------------------
// Launch
// ---------------------------------------------------------------------------
extern "C" void kernel_launch(void* const* d_in, const int* in_sizes, int n_in,
                              void* d_out, int out_size)
{
    const float* x      = (const float*)d_in[0];
    const float* ln1_g  = (const float*)d_in[1];
    const float* ln1_b  = (const float*)d_in[2];
    const float* qk_w   = (const float*)d_in[3];
    const float* v_w    = (const float*)d_in[4];
    const float* proj_w = (const float*)d_in[5];
    const float* proj_b = (const float*)d_in[6];
    const float* ln2_g  = (const float*)d_in[7];
    const float* ln2_b  = (const float*)d_in[8];
    const float* fc1_w  = (const float*)d_in[9];
    const float* fc1_b  = (const float*)d_in[10];
    const float* fc2_w  = (const float*)d_in[11];
    const float* fc2_b  = (const float*)d_in[12];
    float* out = (float*)d_out;

    float *x2;
    __half *qkvh, *h1h, *atth, *h2h, *m1h;
    __half *qkv_wt, *proj_wt, *fc1_wt, *fc2_wt;
    cudaGetSymbolAddress((void**)&qkvh, g_qkvh);
    cudaGetSymbolAddress((void**)&x2,   g_x2);
    cudaGetSymbolAddress((void**)&h1h,  g_h1h);
    cudaGetSymbolAddress((void**)&atth, g_atth);
    cudaGetSymbolAddress((void**)&h2h,  g_h2h);
    cudaGetSymbolAddress((void**)&m1h,  g_m1h);
    cudaGetSymbolAddress((void**)&qkv_wt,  g_qkv_wt);
    cudaGetSymbolAddress((void**)&proj_wt, g_proj_wt);
    cudaGetSymbolAddress((void**)&fc1_wt,  g_fc1_wt);
    cudaGetSymbolAddress((void**)&fc2_wt,  g_fc2_wt);

    static bool attr_done = false;
    if (!attr_done) {
        cudaFuncSetAttribute(flash_h,
                             cudaFuncAttributeMaxDynamicSharedMemorySize,
                             FA_SMEM_BYTES);
        cudaFuncSetAttribute(gemm_h<EPI_NONE, 1>,
                             cudaFuncAttributeMaxDynamicSharedMemorySize,
                             GEMM_SMEM_BYTES);
        cudaFuncSetAttribute(gemm_h<EPI_BIASRES, 0>,
                             cudaFuncAttributeMaxDynamicSharedMemorySize,
                             GEMM_SMEM_BYTES);
        cudaFuncSetAttribute(gemm_h<EPI_GELU, 1>,
                             cudaFuncAttributeMaxDynamicSharedMemorySize,
                             GEMM_SMEM_BYTES);
        attr_done = true;
    }

    // --- weight convert+transpose (~30 us) ---
    wtrans<<<dim3(2 * EMBED / 32, EMBED / 32), 256>>>(qk_w, qkv_wt, EMBED, 2 * EMBED);
    wtrans<<<dim3(EMBED / 32, EMBED / 32), 256>>>(v_w, qkv_wt + (size_t)2 * EMBED * EMBED,
                                                  EMBED, EMBED);
    wtrans<<<dim3(EMBED / 32, EMBED / 32), 256>>>(proj_w, proj_wt, EMBED, EMBED);
    wtrans<<<dim3(MLPDIM / 32, EMBED / 32), 256>>>(fc1_w, fc1_wt, EMBED, MLPDIM);
    wtrans<<<dim3(EMBED / 32, MLPDIM / 32), 256>>>(fc2_w, fc2_wt, MLPDIM, EMBED);

    // --- attention branch ---
    ln_half<<<ROWS / 8, 256>>>(x, ln1_g, ln1_b, h1h);

    gemm_h<EPI_NONE, 1><<<dim3(QKVDIM / 256, ROWS / 128), 256, GEMM_SMEM_BYTES>>>(
        h1h, qkv_wt, nullptr, nullptr, qkvh, ROWS, QKVDIM, EMBED);

    flash_h<<<dim3(SEQ / 128, BH), 256, FA_SMEM_BYTES>>>(qkvh, atth);

    gemm_h<EPI_BIASRES, 0><<<dim3(EMBED / 256, ROWS / 128), 256, GEMM_SMEM_BYTES>>>(
        atth, proj_wt, proj_b, x, x2, ROWS, EMBED, EMBED);

    // --- MLP branch ---
    ln_half<<<ROWS / 8, 256>>>(x2, ln2_g, ln2_b, h2h);

    gemm_h<EPI_GELU, 1><<<dim3(MLPDIM / 256, ROWS / 128), 256, GEMM_SMEM_BYTES>>>(
        h2h, fc1_wt, fc1_b, nullptr, m1h, ROWS, MLPDIM, EMBED);

    gemm_h<EPI_BIASRES, 0><<<dim3(EMBED / 256, ROWS / 128), 256, GEMM_SMEM_BYTES>>>(
        m1h, fc2_wt, fc2_b, x2, out, ROWS, EMBED, MLPDIM);
}

// round 16
// speedup vs baseline: 1.1725x; 1.1725x over previous
#include <cuda_runtime.h>
#include <cuda_fp16.h>
#include <cuda_bf16.h>
#include <math.h>
#include <stdint.h>

// ---------------------------------------------------------------------------
// Problem constants
// ---------------------------------------------------------------------------
#define BATCH   8
#define SEQ     1024
#define ROWS    (BATCH * SEQ)        // 8192
#define EMBED   768
#define HEADS   12
#define HDIM    64
#define QKVDIM  2304                 // fused q|k|v columns
#define MLPDIM  3072
#define BH      (BATCH * HEADS)      // 96

// ---------------------------------------------------------------------------
// Device scratch (static globals — allocation-free)
// ---------------------------------------------------------------------------
__device__ __half g_qkvh[(size_t)ROWS * QKVDIM];     // fused QKV projection (f16)
__device__ float  g_x2  [(size_t)ROWS * EMBED];      // x + proj (f32)
__device__ __half g_h1h [(size_t)ROWS * EMBED];      // LN1 out (f16)
__device__ __half g_atth[(size_t)ROWS * EMBED];      // attention out (f16)
__device__ __half g_h2h [(size_t)ROWS * EMBED];      // LN2 out (f16)
__device__ __half g_m1h [(size_t)ROWS * MLPDIM];     // GELU(fc1) (f16)
__device__ __half g_qkv_wt[(size_t)QKVDIM * EMBED];  // [2304][768] half
__device__ __half g_proj_wt[(size_t)EMBED * EMBED];  // [768][768]
__device__ __half g_fc1_wt[(size_t)MLPDIM * EMBED];  // [3072][768]
__device__ __half g_fc2_wt[(size_t)EMBED * MLPDIM];  // [768][3072]

// ---------------------------------------------------------------------------
// Helpers
// ---------------------------------------------------------------------------
__device__ __forceinline__ void mma_f16(float c[4],
                                        const uint32_t a[4],
                                        const uint32_t b[2]) {
    asm volatile(
        "mma.sync.aligned.m16n8k16.row.col.f32.f16.f16.f32 "
        "{%0,%1,%2,%3}, {%4,%5,%6,%7}, {%8,%9}, {%0,%1,%2,%3};"
        : "+f"(c[0]), "+f"(c[1]), "+f"(c[2]), "+f"(c[3])
        : "r"(a[0]), "r"(a[1]), "r"(a[2]), "r"(a[3]),
          "r"(b[0]), "r"(b[1]));
}

#define LDMX4(r0, r1, r2, r3, addr)                                       \
    asm volatile("ldmatrix.sync.aligned.m8n8.x4.shared.b16 "              \
                 "{%0,%1,%2,%3}, [%4];"                                   \
                 : "=r"(r0), "=r"(r1), "=r"(r2), "=r"(r3) : "r"(addr))

#define LDMX4T(r0, r1, r2, r3, addr)                                      \
    asm volatile("ldmatrix.sync.aligned.m8n8.x4.trans.shared.b16 "        \
                 "{%0,%1,%2,%3}, [%4];"                                   \
                 : "=r"(r0), "=r"(r1), "=r"(r2), "=r"(r3) : "r"(addr))

__device__ __forceinline__ void cp16(uint32_t dst, const void* src) {
    asm volatile("cp.async.cg.shared.global [%0], [%1], 16;" :: "r"(dst), "l"(src));
}
__device__ __forceinline__ void cp_commit() {
    asm volatile("cp.async.commit_group;");
}
__device__ __forceinline__ void cp_wait1() {
    asm volatile("cp.async.wait_group 1;");
}

// ---------------------------------------------------------------------------
// Weight transpose+convert: W [K][N] f32 -> Wt [N][K] f16
// ---------------------------------------------------------------------------
__global__ __launch_bounds__(256)
void wtrans(const float* __restrict__ W, __half* __restrict__ Wt, int K, int N)
{
    __shared__ __half t[32][33];
    const int n0 = blockIdx.x * 32, k0 = blockIdx.y * 32;
    const int tx = threadIdx.x & 31, ty = threadIdx.x >> 5;
    #pragma unroll
    for (int i = 0; i < 4; i++)
        t[ty + i * 8][tx] = __float2half_rn(W[(long)(k0 + ty + i * 8) * N + n0 + tx]);
    __syncthreads();
    #pragma unroll
    for (int i = 0; i < 4; i++)
        Wt[(long)(n0 + ty + i * 8) * K + k0 + tx] = t[tx][ty + i * 8];
}

// ---------------------------------------------------------------------------
// LayerNorm v2 (validated R14): warp per row, float4 loads, shuffle reduce.
// Block 256 = 8 rows. Grid ROWS/8.
// ---------------------------------------------------------------------------
__global__ __launch_bounds__(256)
void ln_half(const float* __restrict__ x, const float* __restrict__ g,
             const float* __restrict__ b, __half* __restrict__ out)
{
    const int lane = threadIdx.x & 31;
    const long row = (long)blockIdx.x * 8 + (threadIdx.x >> 5);
    const float* p = x + row * EMBED;

    float4 v[6];
    float s = 0.0f, q = 0.0f;
    #pragma unroll
    for (int i = 0; i < 6; i++) {
        v[i] = *(const float4*)(p + lane * 4 + i * 128);
        s += v[i].x + v[i].y + v[i].z + v[i].w;
        q += v[i].x * v[i].x + v[i].y * v[i].y + v[i].z * v[i].z + v[i].w * v[i].w;
    }
    #pragma unroll
    for (int o = 16; o; o >>= 1) {
        s += __shfl_xor_sync(0xFFFFFFFFu, s, o);
        q += __shfl_xor_sync(0xFFFFFFFFu, q, o);
    }
    const float inv = 1.0f / (float)EMBED;
    const float mu  = s * inv;
    const float var = q * inv - mu * mu;
    const float rstd = rsqrtf(var + 1e-5f);

    __half* po = out + row * EMBED;
    #pragma unroll
    for (int i = 0; i < 6; i++) {
        const int col = lane * 4 + i * 128;
        const float4 gv = *(const float4*)(g + col);
        const float4 bv = *(const float4*)(b + col);
        __half2 h0 = __floats2half2_rn((v[i].x - mu) * rstd * gv.x + bv.x,
                                       (v[i].y - mu) * rstd * gv.y + bv.y);
        __half2 h1 = __floats2half2_rn((v[i].z - mu) * rstd * gv.z + bv.z,
                                       (v[i].w - mu) * rstd * gv.w + bv.w);
        uint2 u;
        u.x = *(uint32_t*)&h0;
        u.y = *(uint32_t*)&h1;
        *(uint2*)(po + col) = u;
    }
}

// ---------------------------------------------------------------------------
// FP16 ldmatrix GEMM (validated R13): 3-stage cp.async, one barrier/k-tile.
// C = A[M,K] @ Bt[N,K]^T (+ epilogue)
// 128x128 tile, BK=64 halves, 256 threads, warp 64x32, smem stride 72 halves.
// Stage s block @ s*36864 B (A @ +0, B @ +18432). 3 stages = 110592 B.
// ---------------------------------------------------------------------------
#define EPI_NONE     0
#define EPI_GELU     2
#define EPI_BIASRES  3

#define GEMM_SMEM_BYTES 110592

template<int EPI, int OUTH>
__global__ __launch_bounds__(256, 2)
void gemm_h(const __half* __restrict__ A, const __half* __restrict__ Bt,
            const float* __restrict__ bias, const float* __restrict__ res,
            void* __restrict__ Cv, int M, int N, int K)
{
    extern __shared__ __align__(16) uint8_t sgb[];
    const uint32_t sbase = (uint32_t)__cvta_generic_to_shared(sgb);

    const int tid  = threadIdx.x;
    const int bm   = blockIdx.y * 128;
    const int bn   = blockIdx.x * 128;
    const int w    = tid >> 5;
    const int lane = tid & 31;
    const int m0   = (w >> 2) * 64;
    const int n0   = (w & 3) * 32;
    const int g    = lane >> 2;
    const int tq   = lane & 3;

    const int row  = tid >> 1;
    const int side = tid & 1;
    const __half* Ag = A  + (long)(bm + row) * K + side * 32;
    const __half* Bg = Bt + (long)(bn + row) * K + side * 32;
    const uint32_t adst = sbase + row * 144 + side * 64;
    const uint32_t bdst = adst + 18432;

    const int lr = lane & 15, lh = lane >> 4;
    const uint32_t a_lm = sbase + (m0 + lr) * 144 + lh * 16;
    const uint32_t b_lm = sbase + 18432 + (n0 + lr) * 144 + lh * 16;

    float acc[4][4][4];
    #pragma unroll
    for (int i = 0; i < 4; i++)
        #pragma unroll
        for (int j = 0; j < 4; j++)
            #pragma unroll
            for (int r = 0; r < 4; r++) acc[i][j][r] = 0.0f;

    auto issue = [&](int t, int s) {
        const uint32_t off = s * 36864;
        const __half* ap = Ag + t * 64;
        const __half* bp = Bg + t * 64;
        #pragma unroll
        for (int i = 0; i < 4; i++) cp16(adst + off + i * 16, ap + i * 8);
        #pragma unroll
        for (int i = 0; i < 4; i++) cp16(bdst + off + i * 16, bp + i * 8);
    };

    const int NT = K >> 6;           // >= 12 for all our shapes
    issue(0, 0); cp_commit();
    issue(1, 1); cp_commit();

    int st = 0;
    for (int t = 0; t < NT; t++) {
        cp_wait1();                  // tile t landed; tile t+1 in flight
        __syncthreads();             // visibility + stage-(t+2)%3 reads done

        int s2 = st + 2; if (s2 >= 3) s2 -= 3;
        if (t + 2 < NT) issue(t + 2, s2);
        cp_commit();                 // unconditional: exact group accounting

        const uint32_t soff = st * 36864;
        #pragma unroll
        for (int ks = 0; ks < 4; ks++) {
            uint32_t af[4][4];
            #pragma unroll
            for (int i = 0; i < 4; i++)
                LDMX4(af[i][0], af[i][1], af[i][2], af[i][3],
                      a_lm + soff + i * 2304 + ks * 32);
            uint32_t bf[4][2];
            #pragma unroll
            for (int p = 0; p < 2; p++) {
                uint32_t q0, q1, q2, q3;
                LDMX4(q0, q1, q2, q3, b_lm + soff + p * 2304 + ks * 32);
                bf[2 * p    ][0] = q0; bf[2 * p + 1][0] = q1;
                bf[2 * p    ][1] = q2; bf[2 * p + 1][1] = q3;
            }
            #pragma unroll
            for (int i = 0; i < 4; i++)
                #pragma unroll
                for (int j = 0; j < 4; j++)
                    mma_f16(acc[i][j], af[i], bf[j]);
        }
        st = (st == 2) ? 0 : st + 1;
    }

    float*  Cf = (float*)Cv;
    __half* Ch = (__half*)Cv;
    #pragma unroll
    for (int i = 0; i < 4; i++) {
        const int row0 = bm + m0 + i * 16 + g;
        #pragma unroll
        for (int j = 0; j < 4; j++) {
            const int col = bn + n0 + j * 8 + tq * 2;
            float b0 = 0.0f, b1 = 0.0f;
            if (EPI != EPI_NONE) { b0 = bias[col]; b1 = bias[col + 1]; }
            #pragma unroll
            for (int half_ = 0; half_ < 2; half_++) {
                const long base = (long)(row0 + half_ * 8) * N + col;
                float c0 = acc[i][j][half_ * 2 + 0];
                float c1 = acc[i][j][half_ * 2 + 1];
                if (EPI != EPI_NONE) { c0 += b0; c1 += b1; }
                if (EPI == EPI_GELU) {
                    c0 = 0.5f * c0 * (1.0f + erff(c0 * 0.70710678118654752f));
                    c1 = 0.5f * c1 * (1.0f + erff(c1 * 0.70710678118654752f));
                }
                if (EPI == EPI_BIASRES) { c0 += res[base]; c1 += res[base + 1]; }
                if (OUTH) {
                    *(__half2*)(Ch + base) = __floats2half2_rn(c0, c1);
                } else {
                    float2 o; o.x = c0; o.y = c1;
                    *(float2*)(Cf + base) = o;
                }
            }
        }
    }
}

// ---------------------------------------------------------------------------
// Flash attention v5 (validated R13): fp16 ldmatrix + double-buffered K/V.
// Smem bytes: Qs @0 (18432), K stage s @ 18432+s*9216, V stage s @
// 36864+s*9216, Ps @ 55296 (18432). Total 73728 B.
// ---------------------------------------------------------------------------
#define FA_SMEM_BYTES 73728

__global__ __launch_bounds__(256, 2)
void flash_h(const __half* __restrict__ qkv, __half* __restrict__ att)
{
    extern __shared__ __align__(16) uint8_t shb[];
    const uint32_t sbase = (uint32_t)__cvta_generic_to_shared(shb);
    const uint32_t KOFF = 18432;
    const uint32_t VOFF = 36864;
    const uint32_t POFF = 55296;

    const int bh = blockIdx.y;
    const int b  = bh / HEADS, h = bh % HEADS;
    const int q0 = blockIdx.x * 128;
    const int tid  = threadIdx.x;
    const int w    = tid >> 5;
    const int lane = tid & 31;
    const int g    = lane >> 2;
    const int tq   = lane & 3;
    const int lr   = lane & 15, lh = lane >> 4;

    const __half* Qg = qkv + (long)b * SEQ * QKVDIM + h * HDIM;
    const __half* Kg = Qg + EMBED;
    const __half* Vg = Qg + 2 * EMBED;

    const int qrow = tid >> 1, qside = tid & 1;
    const int kr = tid & 63, kq = (tid >> 6) * 16;   // halves

    auto issueKV = [&](int kv, int s) {
        const __half* ks = Kg + (long)(kv + kr) * QKVDIM + kq;
        const __half* vs = Vg + (long)(kv + kr) * QKVDIM + kq;
        const uint32_t kd = sbase + KOFF + s * 9216 + kr * 144 + kq * 2;
        const uint32_t vd = sbase + VOFF + s * 9216 + kr * 144 + kq * 2;
        cp16(kd, ks); cp16(kd + 16, ks + 8);
        cp16(vd, vs); cp16(vd + 16, vs + 8);
    };

    {
        const __half* src = Qg + (long)(q0 + qrow) * QKVDIM + qside * 32;
        const uint32_t dst = sbase + qrow * 144 + qside * 64;
        #pragma unroll
        for (int i = 0; i < 4; i++) cp16(dst + i * 16, src + i * 8);
    }
    issueKV(0, 0);
    cp_commit();

    const uint32_t qa_lm = sbase + (w * 16 + lr) * 144 + lh * 16;
    const uint32_t pa_lm = sbase + POFF + w * 2304 + lr * 144 + lh * 16;
    const uint32_t pw    = sbase + POFF + w * 2304;

    float oacc[8][4];
    #pragma unroll
    for (int j = 0; j < 8; j++)
        #pragma unroll
        for (int r = 0; r < 4; r++) oacc[j][r] = 0.0f;
    float mrow0 = -INFINITY, mrow1 = -INFINITY;
    float lrow0 = 0.0f, lrow1 = 0.0f;

    for (int t = 0; t < SEQ / 64; t++) {
        __syncthreads();             // reads of stage (t+1)&1 (iter t-1) done
        if (t + 1 < SEQ / 64) issueKV((t + 1) * 64, (t + 1) & 1);
        cp_commit();
        cp_wait1();                  // tile t landed (incl. Q on t=0)
        __syncthreads();             // visibility

        const uint32_t kb_lm = sbase + KOFF + (t & 1) * 9216 + lr * 144 + lh * 16;
        const uint32_t vb_lm = sbase + VOFF + (t & 1) * 9216 + lr * 144 + lh * 16;

        float sacc[8][4];
        #pragma unroll
        for (int j = 0; j < 8; j++)
            #pragma unroll
            for (int r = 0; r < 4; r++) sacc[j][r] = 0.0f;

        #pragma unroll
        for (int ks = 0; ks < 4; ks++) {
            uint32_t af[4];
            LDMX4(af[0], af[1], af[2], af[3], qa_lm + ks * 32);
            uint32_t bf[8][2];
            #pragma unroll
            for (int p = 0; p < 4; p++) {
                uint32_t r0, r1, r2, r3;
                LDMX4(r0, r1, r2, r3, kb_lm + p * 2304 + ks * 32);
                bf[2 * p    ][0] = r0; bf[2 * p + 1][0] = r1;
                bf[2 * p    ][1] = r2; bf[2 * p + 1][1] = r3;
            }
            #pragma unroll
            for (int j = 0; j < 8; j++)
                mma_f16(sacc[j], af, bf[j]);
        }

        #pragma unroll
        for (int j = 0; j < 8; j++) {
            sacc[j][0] *= 0.125f; sacc[j][1] *= 0.125f;
            sacc[j][2] *= 0.125f; sacc[j][3] *= 0.125f;
        }
        float tmax0 = -INFINITY, tmax1 = -INFINITY;
        #pragma unroll
        for (int j = 0; j < 8; j++) {
            tmax0 = fmaxf(tmax0, fmaxf(sacc[j][0], sacc[j][1]));
            tmax1 = fmaxf(tmax1, fmaxf(sacc[j][2], sacc[j][3]));
        }
        #pragma unroll
        for (int o = 1; o < 4; o <<= 1) {
            tmax0 = fmaxf(tmax0, __shfl_xor_sync(0xFFFFFFFFu, tmax0, o));
            tmax1 = fmaxf(tmax1, __shfl_xor_sync(0xFFFFFFFFu, tmax1, o));
        }
        const float mnew0 = fmaxf(mrow0, tmax0);
        const float mnew1 = fmaxf(mrow1, tmax1);
        const float alpha0 = __expf(mrow0 - mnew0);
        const float alpha1 = __expf(mrow1 - mnew1);
        mrow0 = mnew0; mrow1 = mnew1;

        float sum0 = 0.0f, sum1 = 0.0f;
        #pragma unroll
        for (int j = 0; j < 8; j++) {
            sacc[j][0] = __expf(sacc[j][0] - mnew0);
            sacc[j][1] = __expf(sacc[j][1] - mnew0);
            sacc[j][2] = __expf(sacc[j][2] - mnew1);
            sacc[j][3] = __expf(sacc[j][3] - mnew1);
            sum0 += sacc[j][0] + sacc[j][1];
            sum1 += sacc[j][2] + sacc[j][3];
        }
        #pragma unroll
        for (int o = 1; o < 4; o <<= 1) {
            sum0 += __shfl_xor_sync(0xFFFFFFFFu, sum0, o);
            sum1 += __shfl_xor_sync(0xFFFFFFFFu, sum1, o);
        }
        lrow0 = lrow0 * alpha0 + sum0;
        lrow1 = lrow1 * alpha1 + sum1;

        #pragma unroll
        for (int j = 0; j < 8; j++) {
            oacc[j][0] *= alpha0; oacc[j][1] *= alpha0;
            oacc[j][2] *= alpha1; oacc[j][3] *= alpha1;
        }

        #pragma unroll
        for (int j = 0; j < 8; j++) {
            __half2 p0 = __floats2half2_rn(sacc[j][0], sacc[j][1]);
            __half2 p1 = __floats2half2_rn(sacc[j][2], sacc[j][3]);
            asm volatile("st.shared.b32 [%0], %1;" ::
                "r"(pw + g * 144 + (j * 8 + tq * 2) * 2),
                "r"(*(uint32_t*)&p0));
            asm volatile("st.shared.b32 [%0], %1;" ::
                "r"(pw + (g + 8) * 144 + (j * 8 + tq * 2) * 2),
                "r"(*(uint32_t*)&p1));
        }
        __syncwarp();

        #pragma unroll
        for (int ks = 0; ks < 4; ks++) {
            uint32_t af[4];
            LDMX4(af[0], af[1], af[2], af[3], pa_lm + ks * 32);
            uint32_t bf[8][2];
            #pragma unroll
            for (int p = 0; p < 4; p++) {
                uint32_t r0, r1, r2, r3;
                LDMX4T(r0, r1, r2, r3, vb_lm + ks * 16 * 144 + p * 32);
                bf[2 * p    ][0] = r0; bf[2 * p    ][1] = r1;
                bf[2 * p + 1][0] = r2; bf[2 * p + 1][1] = r3;
            }
            #pragma unroll
            for (int j = 0; j < 8; j++)
                mma_f16(oacc[j], af, bf[j]);
        }
        __syncwarp();
    }

    const float inv0 = 1.0f / lrow0;
    const float inv1 = 1.0f / lrow1;
    const long row0 = (long)(b * SEQ + q0 + w * 16 + g);
    #pragma unroll
    for (int j = 0; j < 8; j++) {
        const int col = h * HDIM + j * 8 + tq * 2;
        *(__half2*)(att + row0 * EMBED + col) =
            __floats2half2_rn(oacc[j][0] * inv0, oacc[j][1] * inv0);
        *(__half2*)(att + (row0 + 8) * EMBED + col) =
            __floats2half2_rn(oacc[j][2] * inv1, oacc[j][3] * inv1);
    }
}

// ---------------------------------------------------------------------------
// Launch
// ---------------------------------------------------------------------------
extern "C" void kernel_launch(void* const* d_in, const int* in_sizes, int n_in,
                              void* d_out, int out_size)
{
    const float* x      = (const float*)d_in[0];
    const float* ln1_g  = (const float*)d_in[1];
    const float* ln1_b  = (const float*)d_in[2];
    const float* qk_w   = (const float*)d_in[3];
    const float* v_w    = (const float*)d_in[4];
    const float* proj_w = (const float*)d_in[5];
    const float* proj_b = (const float*)d_in[6];
    const float* ln2_g  = (const float*)d_in[7];
    const float* ln2_b  = (const float*)d_in[8];
    const float* fc1_w  = (const float*)d_in[9];
    const float* fc1_b  = (const float*)d_in[10];
    const float* fc2_w  = (const float*)d_in[11];
    const float* fc2_b  = (const float*)d_in[12];
    float* out = (float*)d_out;

    float *x2;
    __half *qkvh, *h1h, *atth, *h2h, *m1h;
    __half *qkv_wt, *proj_wt, *fc1_wt, *fc2_wt;
    cudaGetSymbolAddress((void**)&qkvh, g_qkvh);
    cudaGetSymbolAddress((void**)&x2,   g_x2);
    cudaGetSymbolAddress((void**)&h1h,  g_h1h);
    cudaGetSymbolAddress((void**)&atth, g_atth);
    cudaGetSymbolAddress((void**)&h2h,  g_h2h);
    cudaGetSymbolAddress((void**)&m1h,  g_m1h);
    cudaGetSymbolAddress((void**)&qkv_wt,  g_qkv_wt);
    cudaGetSymbolAddress((void**)&proj_wt, g_proj_wt);
    cudaGetSymbolAddress((void**)&fc1_wt,  g_fc1_wt);
    cudaGetSymbolAddress((void**)&fc2_wt,  g_fc2_wt);

    static bool attr_done = false;
    if (!attr_done) {
        cudaFuncSetAttribute(flash_h,
                             cudaFuncAttributeMaxDynamicSharedMemorySize,
                             FA_SMEM_BYTES);
        cudaFuncSetAttribute(gemm_h<EPI_NONE, 1>,
                             cudaFuncAttributeMaxDynamicSharedMemorySize,
                             GEMM_SMEM_BYTES);
        cudaFuncSetAttribute(gemm_h<EPI_BIASRES, 0>,
                             cudaFuncAttributeMaxDynamicSharedMemorySize,
                             GEMM_SMEM_BYTES);
        cudaFuncSetAttribute(gemm_h<EPI_GELU, 1>,
                             cudaFuncAttributeMaxDynamicSharedMemorySize,
                             GEMM_SMEM_BYTES);
        attr_done = true;
    }

    // --- weight convert+transpose (~15 us) ---
    wtrans<<<dim3(2 * EMBED / 32, EMBED / 32), 256>>>(qk_w, qkv_wt, EMBED, 2 * EMBED);
    wtrans<<<dim3(EMBED / 32, EMBED / 32), 256>>>(v_w, qkv_wt + (size_t)2 * EMBED * EMBED,
                                                  EMBED, EMBED);
    wtrans<<<dim3(EMBED / 32, EMBED / 32), 256>>>(proj_w, proj_wt, EMBED, EMBED);
    wtrans<<<dim3(MLPDIM / 32, EMBED / 32), 256>>>(fc1_w, fc1_wt, EMBED, MLPDIM);
    wtrans<<<dim3(EMBED / 32, MLPDIM / 32), 256>>>(fc2_w, fc2_wt, MLPDIM, EMBED);

    // --- attention branch ---
    ln_half<<<ROWS / 8, 256>>>(x, ln1_g, ln1_b, h1h);

    gemm_h<EPI_NONE, 1><<<dim3(QKVDIM / 128, ROWS / 128), 256, GEMM_SMEM_BYTES>>>(
        h1h, qkv_wt, nullptr, nullptr, qkvh, ROWS, QKVDIM, EMBED);

    flash_h<<<dim3(SEQ / 128, BH), 256, FA_SMEM_BYTES>>>(qkvh, atth);

    gemm_h<EPI_BIASRES, 0><<<dim3(EMBED / 128, ROWS / 128), 256, GEMM_SMEM_BYTES>>>(
        atth, proj_wt, proj_b, x, x2, ROWS, EMBED, EMBED);

    // --- MLP branch ---
    ln_half<<<ROWS / 8, 256>>>(x2, ln2_g, ln2_b, h2h);

    gemm_h<EPI_GELU, 1><<<dim3(MLPDIM / 128, ROWS / 128), 256, GEMM_SMEM_BYTES>>>(
        h2h, fc1_wt, fc1_b, nullptr, m1h, ROWS, MLPDIM, EMBED);

    gemm_h<EPI_BIASRES, 0><<<dim3(EMBED / 128, ROWS / 128), 256, GEMM_SMEM_BYTES>>>(
        m1h, fc2_wt, fc2_b, x2, out, ROWS, EMBED, MLPDIM);
}